// round 17
// baseline (speedup 1.0000x reference)
#include <cuda_runtime.h>
#include <cuda_bf16.h>
#include <cstdint>
#include <cstring>

// GTN collapses (softmax over singleton axis == 1 -> gtconv == 2*A):
//   H   = 4*(A@A) + I
//   inv = 2 / rowsum(H)   (guarded)
//   out = diag(inv) @ (H @ A)
// Fused persistent kernel. R16 mainloop (2-tile k-groups, 6-slot ring).
// This round: global barrier #1 replaced by per-slab ready flags -- each CTA
// starts GEMM1 as soon as its 24 prologue slabs are converted; the full-grid
// convergence spin overlaps the prologue fills.

#define NMAT 2048
static constexpr int BM = 256;
static constexpr int BN = 128;
static constexpr int BK = 32;
static constexpr int KT = NMAT / BK;             // 64 tiles, 32 groups of 2
static constexpr int NSLOT = 6;                  // 3 group-slots x 2 tiles
static constexpr int A_STAGE = BM * 64;          // 16KB (64B rows, M-major)
static constexpr int B_STAGE = BK * 256;         // 8KB  (256B k-rows)
static constexpr int SMEM_B_OFF = NSLOT * A_STAGE;             // 96KB
static constexpr int SMEM_DYN = NSLOT * (A_STAGE + B_STAGE);   // 144KB
static constexpr int NCTA = (NMAT / BN) * (NMAT / BM);         // 128

__device__ __nv_bfloat16 g_Abf[(size_t)NMAT * NMAT];
__device__ __nv_bfloat16 g_Hbf[(size_t)NMAT * NMAT];
__device__ float g_rowpart[4][NMAT / BN][NMAT];
__device__ unsigned g_bar_cnt = 0;
__device__ unsigned g_bar_gen = 0;
__device__ unsigned g_slab_flag[NCTA] = {};   // slab s converted when >= target

__device__ __forceinline__ uint32_t smem_u32(const void* p) {
    uint32_t a;
    asm("{ .reg .u64 t; cvta.to.shared.u64 t, %1; cvt.u32.u64 %0, t; }" : "=r"(a) : "l"(p));
    return a;
}
#define CP_ASYNC16(dst, src) asm volatile("cp.async.cg.shared.global [%0], [%1], 16;" :: "r"(dst), "l"(src) : "memory")
#define CP_COMMIT()          asm volatile("cp.async.commit_group;" ::: "memory")
#define CP_WAIT1()           asm volatile("cp.async.wait_group 1;" ::: "memory")
#define CP_WAIT0()           asm volatile("cp.async.wait_group 0;" ::: "memory")
#define LDSM_X4(r0, r1, r2, r3, a) \
    asm volatile("ldmatrix.sync.aligned.m8n8.x4.shared.b16 {%0,%1,%2,%3}, [%4];" \
                 : "=r"(r0), "=r"(r1), "=r"(r2), "=r"(r3) : "r"(a))
#define LDSM_X4T(r0, r1, r2, r3, a) \
    asm volatile("ldmatrix.sync.aligned.m8n8.x4.trans.shared.b16 {%0,%1,%2,%3}, [%4];" \
                 : "=r"(r0), "=r"(r1), "=r"(r2), "=r"(r3) : "r"(a))
#define MMA_BF16(c, a, b) \
    asm volatile("mma.sync.aligned.m16n8k16.row.col.f32.bf16.bf16.f32 " \
                 "{%0,%1,%2,%3}, {%4,%5,%6,%7}, {%8,%9}, {%0,%1,%2,%3};" \
                 : "+f"((c)[0]), "+f"((c)[1]), "+f"((c)[2]), "+f"((c)[3]) \
                 : "r"((a)[0]), "r"((a)[1]), "r"((a)[2]), "r"((a)[3]), "r"((b)[0]), "r"((b)[1]))

__device__ __forceinline__ uint32_t swzA(int row, int colb) {
    return (uint32_t)(row * 64 + (colb ^ (((row >> 1) & 3) << 4)));
}
__device__ __forceinline__ uint32_t swzB(int k, int chunk) {
    return (uint32_t)(k * 256 + ((chunk ^ (k & 7)) << 4));
}
__device__ __forceinline__ uint32_t bf2_bits(__nv_bfloat162 v) {
    uint32_t u; memcpy(&u, &v, 4); return u;
}
__device__ __forceinline__ int tile_slot(int t) {
    return 2 * ((t >> 1) % 3) + (t & 1);
}
__device__ __forceinline__ void spin_flag(const unsigned* f, unsigned target) {
    while (*(volatile const unsigned*)f < target) {}
}

// Self-resetting global barrier (128 CTAs co-resident at 1 CTA/SM: safe).
__device__ __forceinline__ void grid_barrier() {
    __syncthreads();
    if (threadIdx.x == 0) {
        __threadfence();
        volatile unsigned* genp = &g_bar_gen;
        const unsigned g = *genp;
        const unsigned my = atomicAdd(&g_bar_cnt, 1u);
        if (my == NCTA - 1) {
            *(volatile unsigned*)&g_bar_cnt = 0u;
            __threadfence();
            *genp = g + 1u;
        } else {
            while (*genp == g) {}
        }
        __threadfence();
    }
    __syncthreads();
}

// ---------------- GEMM body (R16 mainloop) ----------------
// MODE 0: L = g_Abf ; H = 4D + I -> g_Hbf + row partials. flag_target gates
//         the full-convert spin (overlapped with prologue fills).
// MODE 1: L = g_Hbf ; out = s_inv[r]*D.
template <int MODE>
__device__ __forceinline__ void gemm_body(float* __restrict__ Cout,
                                          const uint32_t sb,
                                          const int bx, const int by,
                                          const unsigned flag_target)
{
    __shared__ float s_inv[BM];

    const int tid = threadIdx.x;
    const int lane = tid & 31;
    const int wid = tid >> 5;
    const int warp_m = wid & 3;
    const int warp_n = wid >> 2;
    const int row0 = by * BM;
    const int col0 = bx * BN;

    const __nv_bfloat16* __restrict__ Lop = (MODE == 0) ? g_Abf : g_Hbf;
    const __nv_bfloat16* __restrict__ Rop = g_Abf;   // B = A k-rows, both modes

    uint32_t abase[2];
#pragma unroll
    for (int st = 0; st < 2; st++)
        abase[st] = swzA(warp_m * 64 + (lane & 15), st * 32 + ((lane >> 4) << 4));

    uint32_t bbase[2][2];
    {
        const int m = lane >> 3, r = lane & 7;
#pragma unroll
        for (int st = 0; st < 2; st++)
#pragma unroll
            for (int np = 0; np < 2; np++)
                bbase[st][np] = swzB(st * 16 + ((m & 1) << 3) + r,
                                     warp_n * 4 + np * 2 + (m >> 1));
    }

    auto fill = [&](int t) {
        const int slot = tile_slot(t);
        const uint32_t ab = sb + slot * A_STAGE;
        const uint32_t bb = sb + SMEM_B_OFF + slot * B_STAGE;
#pragma unroll
        for (int i = 0; i < 2; i++) {
            const int ch = i * 512 + tid;
            const int row = ch >> 2, c16 = ch & 3;
            CP_ASYNC16(ab + swzA(row, c16 * 16),
                       Lop + (size_t)(row0 + row) * NMAT + t * BK + c16 * 8);
        }
        {
            const int krow = tid >> 4, c = tid & 15;
            CP_ASYNC16(bb + swzB(krow, c),
                       Rop + (size_t)(t * BK + krow) * NMAT + col0 + c * 8);
        }
    };

    float acc[4][4][4];
#pragma unroll
    for (int mt = 0; mt < 4; mt++)
#pragma unroll
        for (int nt = 0; nt < 4; nt++)
#pragma unroll
            for (int j = 0; j < 4; j++) acc[mt][nt][j] = 0.f;

    // Prologue: groups 0 (tiles 0,1) and 1 (tiles 2,3). For MODE 0 the caller
    // guaranteed the 24 slabs these fills touch are converted.
    fill(0); fill(1); CP_COMMIT();
    fill(2); fill(3); CP_COMMIT();

    if (MODE == 0) {
        // Wait for ALL slabs (mainloop fills touch arbitrary k-slabs) while
        // the prologue fills fly. The mainloop's first __syncthreads orders
        // every thread after this spin before any tile>=4 fill is issued.
        if (tid < NCTA) spin_flag(&g_slab_flag[tid], flag_target);
    }

    if (MODE == 1 && tid < BM) {
        const int r = row0 + tid;
        float d = 0.f;
#pragma unroll
        for (int h = 0; h < 4; h++)
#pragma unroll
            for (int t = 0; t < NMAT / BN; t++) d += g_rowpart[h][t][r];
        if (d <= 1e-10f) d = 1.f;
        s_inv[tid] = 2.f / d;
    }
    // s_inv visibility: the mainloop's __syncthreads() (KT >= 2).

    auto do_tile_step = [&](const uint32_t ab, const uint32_t bb, int st) {
        uint32_t a[4][4], b[2][4];
#pragma unroll
        for (int mt = 0; mt < 4; mt++)
            LDSM_X4(a[mt][0], a[mt][1], a[mt][2], a[mt][3], ab + abase[st] + mt * 1024);
#pragma unroll
        for (int np = 0; np < 2; np++)
            LDSM_X4T(b[np][0], b[np][1], b[np][2], b[np][3], bb + bbase[st][np]);
#pragma unroll
        for (int mt = 0; mt < 4; mt++)
#pragma unroll
            for (int nt = 0; nt < 4; nt++) {
                uint32_t bf[2] = {b[nt >> 1][(nt & 1) * 2], b[nt >> 1][(nt & 1) * 2 + 1]};
                MMA_BF16(acc[mt][nt], a[mt], bf);
            }
    };

    // Mainloop: 32 iterations of 2 tiles; ONE wait + ONE syncthreads each.
    for (int kt = 0; kt < KT; kt += 2) {
        CP_WAIT1();
        __syncthreads();

        const int s0 = tile_slot(kt);
        const int s1 = tile_slot(kt + 1);
        const uint32_t ab0 = sb + s0 * A_STAGE;
        const uint32_t bb0 = sb + SMEM_B_OFF + s0 * B_STAGE;
        const uint32_t ab1 = sb + s1 * A_STAGE;
        const uint32_t bb1 = sb + SMEM_B_OFF + s1 * B_STAGE;

        do_tile_step(ab0, bb0, 0);

        if (kt + 4 < KT) { fill(kt + 4); fill(kt + 5); }
        CP_COMMIT();

        do_tile_step(ab0, bb0, 1);
        do_tile_step(ab1, bb1, 0);
        do_tile_step(ab1, bb1, 1);
    }
    CP_WAIT0();   // drain before smem reuse in the next phase

    // ---------------- epilogue ----------------
#pragma unroll
    for (int mt = 0; mt < 4; mt++) {
        const int rA = row0 + warp_m * 64 + mt * 16 + (lane >> 2);
        const float s0 = (MODE == 0) ? 4.0f : s_inv[rA - row0];
        const float s1 = (MODE == 0) ? 4.0f : s_inv[rA + 8 - row0];
        float rs0 = 0.f, rs1 = 0.f;
#pragma unroll
        for (int nt = 0; nt < 4; nt++) {
            const int c = col0 + warp_n * 32 + nt * 8 + (lane & 3) * 2;
            float v0 = s0 * acc[mt][nt][0];
            float v1 = s0 * acc[mt][nt][1];
            float v2 = s1 * acc[mt][nt][2];
            float v3 = s1 * acc[mt][nt][3];
            if (MODE == 0) {
                if (rA == c)         v0 += 1.0f;
                if (rA == c + 1)     v1 += 1.0f;
                if (rA + 8 == c)     v2 += 1.0f;
                if (rA + 8 == c + 1) v3 += 1.0f;
                rs0 += v0 + v1;
                rs1 += v2 + v3;
                *reinterpret_cast<__nv_bfloat162*>(g_Hbf + (size_t)rA * NMAT + c) =
                    __floats2bfloat162_rn(v0, v1);
                *reinterpret_cast<__nv_bfloat162*>(g_Hbf + (size_t)(rA + 8) * NMAT + c) =
                    __floats2bfloat162_rn(v2, v3);
            } else {
                *reinterpret_cast<float2*>(Cout + (size_t)rA * NMAT + c) = make_float2(v0, v1);
                *reinterpret_cast<float2*>(Cout + (size_t)(rA + 8) * NMAT + c) = make_float2(v2, v3);
            }
        }
        if (MODE == 0) {
            rs0 += __shfl_xor_sync(0xFFFFFFFF, rs0, 1);
            rs0 += __shfl_xor_sync(0xFFFFFFFF, rs0, 2);
            rs1 += __shfl_xor_sync(0xFFFFFFFF, rs1, 1);
            rs1 += __shfl_xor_sync(0xFFFFFFFF, rs1, 2);
            if ((lane & 3) == 0) {
                g_rowpart[warp_n][bx][rA] = rs0;
                g_rowpart[warp_n][bx][rA + 8] = rs1;
            }
        }
    }
}

// ---------------- fused persistent kernel ----------------
__global__ __launch_bounds__(512, 1)
void gtn_fused(const float* __restrict__ A, float* __restrict__ out)
{
    extern __shared__ char dyn_raw[];
    const uint32_t sb = smem_u32(dyn_raw);
    const int bid = blockIdx.x;
    const int tid = threadIdx.x;
    const int bx = bid & 15, by = bid >> 4;

    __shared__ unsigned s_gen;

    // Phase 0: convert this CTA's 16-row slab of A to bf16 (coalesced),
    // then publish via per-slab generation flag (monotonic -> replay-safe).
    if (tid == 0) s_gen = g_slab_flag[bid];
    __syncthreads();
    {
        const float4* __restrict__ A4 =
            reinterpret_cast<const float4*>(A) + (size_t)bid * 8192;
        uint2* __restrict__ O2 =
            reinterpret_cast<uint2*>(g_Abf) + (size_t)bid * 8192;
#pragma unroll
        for (int i = 0; i < 16; i++) {
            const int idx = i * 512 + tid;
            const float4 v = A4[idx];
            uint2 o;
            o.x = bf2_bits(__floats2bfloat162_rn(v.x, v.y));
            o.y = bf2_bits(__floats2bfloat162_rn(v.z, v.w));
            O2[idx] = o;
        }
    }
    __threadfence();            // each thread orders its own slab stores
    __syncthreads();            // all stores fenced before flag publish
    const unsigned target = s_gen + 1u;
    if (tid == 0) *(volatile unsigned*)&g_slab_flag[bid] = target;

    // Wait only for the 24 slabs GEMM1's prologue (tiles 0..3) touches:
    // A operand: stripe slabs 16*by..16*by+15; B operand: k-slabs 0..7.
    if (tid < 16)       spin_flag(&g_slab_flag[16 * by + tid], target);
    else if (tid < 24)  spin_flag(&g_slab_flag[tid - 16], target);
    __syncthreads();

    gemm_body<0>(out, sb, bx, by, target);   // H = 4*A@A + I -> g_Hbf + rowparts
    grid_barrier();                          // g_Hbf + g_rowpart visible
    gemm_body<1>(out, sb, bx, by, target);   // out = diag(2/deg) @ (H @ A)
}

extern "C" void kernel_launch(void* const* d_in, const int* in_sizes, int n_in,
                              void* d_out, int out_size)
{
    const float* A = (const float*)d_in[0];   // weights unused: softmax over singleton == 1
    float* out = (float*)d_out;

    cudaFuncSetAttribute(gtn_fused, cudaFuncAttributeMaxDynamicSharedMemorySize, SMEM_DYN);
    gtn_fused<<<NCTA, 512, SMEM_DYN>>>(A, out);
}